// round 11
// baseline (speedup 1.0000x reference)
#include <cuda_runtime.h>
#include <math.h>

// Problem constants
#define LNUM 196      // H*W
#define BTN  128      // B*T
#define DIM  768
#define NDH  64
#define NT   8
#define NB   16
#define NH   14
#define NLW  5
#define NROWS 25088   // LNUM*BTN
#define NF   640      // B*T*Lw frames
#define PIXC 15876    // 196*81

typedef unsigned long long ull;

// ---------------- scratch (device globals: allocation-free) ----------------
__device__ float g_Wg[NDH * DIM];
__device__ float g_A[NDH];
__device__ float g_Bc[NDH];
__device__ float g_fn[BTN * LNUM * NDH];          // normalized features [bt][pix][c]
__device__ float g_corr[(size_t)NF * PIXC];        // [frame][pix][81]
__device__ float g_yext[80 * 64 * 8 * 196];        // [(b*5+l)*64+c][t][pix]
__device__ float g_y0[80 * 64 * 8 * 196];
__device__ float g_y1[80 * 64 * 8 * 196];
__device__ float g_y2[16 * 64 * 8 * 196];          // [(b*64+c)][t][pix]
__device__ float g_y2t[(size_t)NROWS * 64];        // [(pix*128+bt)][c]
// Winograd-transformed weights U = G g G^T : [fr=16][ci2][co=64][2]
__device__ float g_u0[16 * 32 * 64 * 2];
__device__ float g_u1[16 * 32 * 64 * 2];
__device__ float g_u2[16 * 160 * 64 * 2];

__device__ __forceinline__ float gelu_exact(float x) {
    return 0.5f * x * (1.0f + erff(x * 0.70710678118654752f));
}

// ---- packed f32x2 helpers (FFMA2: saves issue slots) ----
__device__ __forceinline__ void ffma2(ull& d, ull a, ull b) {
    asm("fma.rn.f32x2 %0, %1, %2, %0;" : "+l"(d) : "l"(a), "l"(b));
}
__device__ __forceinline__ ull pack2(float lo, float hi) {
    ull r; asm("mov.b64 %0, {%1, %2};" : "=l"(r) : "f"(lo), "f"(hi)); return r;
}
__device__ __forceinline__ float2 unpack2(ull v) {
    float lo, hi; asm("mov.b64 {%0, %1}, %2;" : "=f"(lo), "=f"(hi) : "l"(v));
    return make_float2(lo, hi);
}

// ---------------- kernel 0: fold layernorm gamma/beta into projection ------
__global__ void prep_w_kernel(const float* __restrict__ in_w,
                              const float* __restrict__ gamma,
                              const float* __restrict__ beta,
                              const float* __restrict__ in_b) {
    int c = blockIdx.x;
    int tid = threadIdx.x;
    float pa = 0.f, pb = 0.f;
    for (int d = tid; d < DIM; d += 256) {
        float w  = in_w[c * DIM + d];
        float wg = w * gamma[d];
        g_Wg[c * DIM + d] = wg;
        pa += wg;
        pb += w * beta[d];
    }
    __shared__ float rA[256], rB[256];
    rA[tid] = pa; rB[tid] = pb;
    __syncthreads();
    for (int s = 128; s > 0; s >>= 1) {
        if (tid < s) { rA[tid] += rA[tid + s]; rB[tid] += rB[tid + s]; }
        __syncthreads();
    }
    if (tid == 0) { g_A[c] = rA[0]; g_Bc[c] = rB[0] + in_b[c]; }
}

// ---------------- kernel 0b: Winograd weight transform ---------------------
__device__ __forceinline__ void wino_u_store(const float* __restrict__ g,
                                             float* __restrict__ U,
                                             int ci, int co, int CI2T) {
    float q[4][3];
#pragma unroll
    for (int c = 0; c < 3; c++) {
        float g0 = g[c], g1 = g[3 + c], g2 = g[6 + c];
        q[0][c] = g0;
        q[1][c] = 0.5f * (g0 + g1 + g2);
        q[2][c] = 0.5f * (g0 - g1 + g2);
        q[3][c] = g2;
    }
#pragma unroll
    for (int r = 0; r < 4; r++) {
        float uu[4];
        uu[0] = q[r][0];
        uu[1] = 0.5f * (q[r][0] + q[r][1] + q[r][2]);
        uu[2] = 0.5f * (q[r][0] - q[r][1] + q[r][2]);
        uu[3] = q[r][2];
#pragma unroll
        for (int c = 0; c < 4; c++) {
            int frq = r * 4 + c;
            U[(((size_t)frq * CI2T + (ci >> 1)) * 64 + co) * 2 + (ci & 1)] = uu[c];
        }
    }
}
__global__ void wino_w_kernel(const float* __restrict__ i0w,
                              const float* __restrict__ i1w,
                              const float* __restrict__ i2w) {
    int t = blockIdx.x * 256 + threadIdx.x;
    if (t < 4096) {
        int co = t & 63, ci = t >> 6;
        wino_u_store(i0w + (co * 64 + ci) * 9, g_u0, ci, co, 32);
        wino_u_store(i1w + (co * 64 + ci) * 9, g_u1, ci, co, 32);
    }
    if (t < 20480) {
        int co = t & 63, ci = t >> 6;
        wino_u_store(i2w + (co * 320 + ci) * 9, g_u2, ci, co, 160);
    }
}

// ---------------- kernel 2: input GEMM + fused LN stats + normalize --------
__global__ void gemm_in_kernel(const float* __restrict__ x) {
    __shared__ float XsT[32 * 72];
    __shared__ float WsT[32 * 72];
    __shared__ float Sv[64][65];
    __shared__ float Srow[64][4];
    __shared__ float Sinv[64];
    __shared__ float s_mu[64];
    __shared__ float s_rs[64];
    int tid = threadIdx.x;
    int ty = tid >> 4, tx = tid & 15;
    int w = tid >> 5, lane = tid & 31;
    int row0 = blockIdx.x * 64;
    ull acc2[2][4] = {};
    float sumv[8] = {}, sqv[8] = {};
    float xr[8], wr[8];
#pragma unroll
    for (int i = 0; i < 8; i++) {
        int e = tid + i * 256;
        int r = e >> 5, k = e & 31;
        xr[i] = x[(size_t)(row0 + r) * DIM + k];
        wr[i] = g_Wg[r * DIM + k];
    }
    for (int kb = 0; kb < DIM; kb += 32) {
#pragma unroll
        for (int i = 0; i < 8; i++) {
            int e = tid + i * 256;
            int r = e >> 5, k = e & 31;
            XsT[k * 72 + r] = xr[i];
            WsT[k * 72 + r] = wr[i];
            sumv[i] += xr[i];
            sqv[i]  += xr[i] * xr[i];
        }
        __syncthreads();
        if (kb + 32 < DIM) {
#pragma unroll
            for (int i = 0; i < 8; i++) {
                int e = tid + i * 256;
                int r = e >> 5, k = e & 31;
                xr[i] = x[(size_t)(row0 + r) * DIM + kb + 32 + k];
                wr[i] = g_Wg[r * DIM + kb + 32 + k];
            }
        }
#pragma unroll 4
        for (int k = 0; k < 32; k++) {
            ulonglong2 a2 = *(const ulonglong2*)(XsT + k * 72 + ty * 4);
            float4 bq = *(const float4*)(WsT + k * 72 + tx * 4);
            ull b0 = pack2(bq.x, bq.x), b1 = pack2(bq.y, bq.y);
            ull b2 = pack2(bq.z, bq.z), b3 = pack2(bq.w, bq.w);
            ffma2(acc2[0][0], a2.x, b0); ffma2(acc2[0][1], a2.x, b1);
            ffma2(acc2[0][2], a2.x, b2); ffma2(acc2[0][3], a2.x, b3);
            ffma2(acc2[1][0], a2.y, b0); ffma2(acc2[1][1], a2.y, b1);
            ffma2(acc2[1][2], a2.y, b2); ffma2(acc2[1][3], a2.y, b3);
        }
        __syncthreads();
    }
#pragma unroll
    for (int i = 0; i < 8; i++) {
        for (int o = 16; o > 0; o >>= 1) {
            sumv[i] += __shfl_xor_sync(0xffffffffu, sumv[i], o);
            sqv[i]  += __shfl_xor_sync(0xffffffffu, sqv[i],  o);
        }
    }
    if (lane == 0) {
#pragma unroll
        for (int i = 0; i < 8; i++) {
            int r = w + 8 * i;
            float mu  = sumv[i] * (1.0f / DIM);
            float var = sqv[i] * (1.0f / DIM) - mu * mu;
            s_mu[r] = mu;
            s_rs[r] = rsqrtf(var + 1e-5f);
        }
    }
    __syncthreads();
    float accf[4][4];
#pragma unroll
    for (int i2 = 0; i2 < 2; i2++)
#pragma unroll
        for (int j = 0; j < 4; j++) {
            float2 v = unpack2(acc2[i2][j]);
            accf[2 * i2][j] = v.x;
            accf[2 * i2 + 1][j] = v.y;
        }
#pragma unroll
    for (int i = 0; i < 4; i++) {
        int rl = ty * 4 + i;
        float rs = s_rs[rl], mu = s_mu[rl];
#pragma unroll
        for (int j = 0; j < 4; j++) {
            int c = tx * 4 + j;
            Sv[rl][c] = rs * accf[i][j] - rs * mu * g_A[c] + g_Bc[c];
        }
    }
    __syncthreads();
    {
        int row = tid >> 2, q = tid & 3;
        float s = 0.f;
#pragma unroll
        for (int c = 0; c < 16; c++) { float v = Sv[row][q * 16 + c]; s += v * v; }
        Srow[row][q] = s;
    }
    __syncthreads();
    if (tid < 64) {
        float n = Srow[tid][0] + Srow[tid][1] + Srow[tid][2] + Srow[tid][3];
        Sinv[tid] = 1.0f / fmaxf(sqrtf(n), 1e-7f);
    }
    __syncthreads();
#pragma unroll
    for (int i = 0; i < 16; i++) {
        int e = tid + i * 256;
        int row = e >> 6, c = e & 63;
        int r = row0 + row;
        int l = r >> 7, bt = r & 127;
        g_fn[((size_t)bt * LNUM + l) * NDH + c] = Sv[row][c] * Sinv[row];
    }
}

// ---------------- kernel 3: local 9x9 correlation (FFMA2, pair smem) -------
__global__ void corr_kernel() {
    extern __shared__ float s_tgt[];
    int fidx = blockIdx.x;
    int b = fidx / 40, rem = fidx % 40;
    int t = rem / 5, l = rem % 5;
    int ttg = t + l - 2;
    float* outp = g_corr + (size_t)fidx * PIXC;
    int tid = threadIdx.x;
    if (ttg < 0 || ttg >= NT) {
        for (int e = tid; e < PIXC; e += 224) outp[e] = 0.0f;
        return;
    }
    const float* tgt = g_fn + (size_t)(b * 8 + ttg) * (196 * 64);
    for (int e = tid; e < 3136; e += 224) {
        int p = e >> 4, c4 = e & 15;
        float4 v = *(const float4*)(tgt + p * 64 + c4 * 4);
        *(float2*)(s_tgt + (c4 * 2 + 0) * 392 + 2 * p) = make_float2(v.x, v.y);
        *(float2*)(s_tgt + (c4 * 2 + 1) * 392 + 2 * p) = make_float2(v.z, v.w);
    }
    __syncthreads();
    if (tid < 196) {
        int h = tid / 14, w = tid % 14;
        const float4* src = (const float4*)(g_fn + ((size_t)(b * 8 + t) * 196 + tid) * 64);
        ull s2[32];
#pragma unroll
        for (int i = 0; i < 16; i++) {
            float4 v = src[i];
            s2[i * 2 + 0] = pack2(v.x, v.y);
            s2[i * 2 + 1] = pack2(v.z, v.w);
        }
        float* op = outp + tid * 81;
#pragma unroll 1
        for (int du = 0; du < 9; du++) {
            int uh = h + du - 4;
            bool rok = (uh >= 0) && (uh < 14);
#pragma unroll 1
            for (int dv = 0; dv < 9; dv++) {
                int vw = w + dv - 4;
                float acc = 0.0f;
                if (rok && vw >= 0 && vw < 14) {
                    const float* tp = s_tgt + 2 * (uh * 14 + vw);
                    ull a2 = 0ull;
#pragma unroll
                    for (int c2 = 0; c2 < 32; c2++) {
                        ull tv = *(const ull*)(tp + c2 * 392);
                        ffma2(a2, s2[c2], tv);
                    }
                    float2 r = unpack2(a2);
                    acc = r.x + r.y;
                }
                op[du * 9 + dv] = acc;
            }
        }
    }
}

// ---------------- kernel 4: ext 1x1 (81->64) + BN + GELU, 7px x 4co tile ---
__global__ void ext_kernel(const float* __restrict__ ew,
                           const float* __restrict__ scale,
                           const float* __restrict__ shift) {
    extern __shared__ float sm[];
    float* sw = sm;           // [k=81][co=64]  = 5184
    float* sc = sm + 5184;    // [pl=98][k=81]  = 7938
    int fidx = blockIdx.x;
    int pix0 = blockIdx.y * 98;
    int b = fidx / 40, rem = fidx % 40, t = rem / 5, l = rem % 5;
    int tid = threadIdx.x;
    for (int e = tid; e < 5184; e += 224) {
        int k = e >> 6, co = e & 63;
        sw[e] = ew[co * 81 + k];
    }
    const float* cp = g_corr + (size_t)fidx * PIXC + (size_t)pix0 * 81;
    for (int e = tid; e < 7938; e += 224) sc[e] = cp[e];
    __syncthreads();
    int plg = tid >> 4, coq = tid & 15;
    float acc[7][4] = {};
    const float* scp = sc + plg * 7 * 81;
    const float* swp = sw + coq * 4;
#pragma unroll 3
    for (int k = 0; k < 81; k++) {
        float4 wq = *(const float4*)(swp + k * 64);
#pragma unroll
        for (int i = 0; i < 7; i++) {
            float cv = scp[i * 81 + k];
            acc[i][0] += cv * wq.x;
            acc[i][1] += cv * wq.y;
            acc[i][2] += cv * wq.z;
            acc[i][3] += cv * wq.w;
        }
    }
    size_t obase = ((size_t)(b * 5 + l) * 64) * 1568 + (size_t)t * 196 + pix0 + plg * 7;
#pragma unroll
    for (int j = 0; j < 4; j++) {
        int co = coq * 4 + j;
        float scv = scale[co], shv = shift[co];
#pragma unroll
        for (int i = 0; i < 7; i++)
            g_yext[obase + (size_t)co * 1568 + i] = gelu_exact(acc[i][j] * scv + shv);
    }
}

// ---------------- Winograd F(2x2,3x3) conv kernels -------------------------
// WHICH: 0 = yext->y0, 1 = y0->y1, 2 = y1->y2 (320 ci)
// CTA = (slice, co-group of 16). 896 threads = 16 fr x 8 coq(2 co) x 7 tg(7 tiles).
// smem: s_in [16ci][16x16] = 4096 | s_V [16fr][tiles*18+ci] = 14336 | s_U 4096
template <int WHICH>
__global__ void __launch_bounds__(896, 1)
wino_conv_kernel(const float* __restrict__ scale,
                 const float* __restrict__ shift) {
    constexpr int NCI  = (WHICH == 2) ? 320 : 64;
    constexpr int NCH  = NCI / 16;
    constexpr int CI2T = NCI / 2;
    const float* in  = (WHICH == 0) ? g_yext : (WHICH == 1) ? g_y0 : g_y1;
    const float* Ug  = (WHICH == 0) ? g_u0   : (WHICH == 1) ? g_u1 : g_u2;
    float*       out = (WHICH == 0) ? g_y0   : (WHICH == 1) ? g_y1 : g_y2;
    extern __shared__ float sm[];
    float* s_in = sm;           // 4096
    float* s_V  = sm + 4096;    // 14336
    float* s_U  = sm + 18432;   // 4096
    int tid = threadIdx.x;
    int cog = blockIdx.y;
    size_t ibase, obase;
    if (WHICH == 2) {
        int b = blockIdx.x >> 3, t = blockIdx.x & 7;
        ibase = (size_t)b * 501760 + (size_t)t * 196;   // ((b*320+ci)*8+t)*196 - ci*1568
        obase = (size_t)(b * 512 + t) * 196;
    } else {
        int f = blockIdx.x >> 3, t = blockIdx.x & 7;
        ibase = (size_t)(f * 512 + t) * 196;
        obase = ibase;
    }
    int fr  = tid / 56;
    int rem = tid - fr * 56;
    int coq = rem / 7;
    int tg  = rem - coq * 7;
    ull macc[7][2] = {};
    for (int e = tid; e < 4096; e += 896) s_in[e] = 0.0f;   // halo stays 0 across chunks
    for (int cb = 0; cb < NCH; cb++) {
        __syncthreads();
        for (int e = tid; e < 3136; e += 896) {
            int c = e / 196, p = e - c * 196;
            s_in[c * 256 + (p / 14 + 1) * 16 + (p % 14) + 1] =
                in[ibase + (size_t)(cb * 16 + c) * 1568 + p];
        }
        {
            const ull* su = (const ull*)Ug;
            ull* du = (ull*)s_U;
            for (int e = tid; e < 2048; e += 896) {
                int f2 = e >> 7, r = e & 127;
                du[e] = su[((size_t)f2 * CI2T + cb * 8 + (r >> 4)) * 64 + cog * 16 + (r & 15)];
            }
        }
        __syncthreads();
        if (tid < 784) {   // input transform: V = B^T d B
            int tile = tid >> 4, ci = tid & 15;
            int ti = tile / 7, tj = tile - ti * 7;
            const float* dp = s_in + ci * 256 + (2 * ti) * 16 + 2 * tj;
            float d[4][4];
#pragma unroll
            for (int r = 0; r < 4; r++)
#pragma unroll
                for (int c = 0; c < 4; c++) d[r][c] = dp[r * 16 + c];
            float a[4][4];
#pragma unroll
            for (int c = 0; c < 4; c++) {
                a[0][c] = d[0][c] - d[2][c];
                a[1][c] = d[1][c] + d[2][c];
                a[2][c] = d[2][c] - d[1][c];
                a[3][c] = d[1][c] - d[3][c];
            }
            int bv = tile * 18 + ci;
#pragma unroll
            for (int r = 0; r < 4; r++) {
                s_V[(r * 4 + 0) * 896 + bv] = a[r][0] - a[r][2];
                s_V[(r * 4 + 1) * 896 + bv] = a[r][1] + a[r][2];
                s_V[(r * 4 + 2) * 896 + bv] = a[r][2] - a[r][1];
                s_V[(r * 4 + 3) * 896 + bv] = a[r][1] - a[r][3];
            }
        }
        __syncthreads();
        {   // frequency GEMM, ci-pair FFMA2
            const float* vb = s_V + fr * 896 + tg * 126;
            const ull* ub = (const ull*)s_U + fr * 128 + coq * 2;
#pragma unroll
            for (int c2 = 0; c2 < 8; c2++) {
                ulonglong2 uq = *(const ulonglong2*)(ub + c2 * 16);
                const ull* vp = (const ull*)(vb + c2 * 2);
#pragma unroll
                for (int i = 0; i < 7; i++) {
                    ull v = vp[i * 9];
                    ffma2(macc[i][0], v, uq.x);
                    ffma2(macc[i][1], v, uq.y);
                }
            }
        }
    }
    __syncthreads();
    // write M to smem (reuse s_V), layout [(tile*16+co)*17 + fr]
#pragma unroll
    for (int i = 0; i < 7; i++)
#pragma unroll
        for (int j = 0; j < 2; j++) {
            float2 v = unpack2(macc[i][j]);
            s_V[((tg * 7 + i) * 16 + coq * 2 + j) * 17 + fr] = v.x + v.y;
        }
    __syncthreads();
    if (tid < 784) {   // output transform: Y = A^T M A, + BN-GELU
        int tile = tid >> 4, col = tid & 15;
        int ti = tile / 7, tj = tile - ti * 7;
        const float* mp = s_V + (tile * 16 + col) * 17;
        float m[16];
#pragma unroll
        for (int f2 = 0; f2 < 16; f2++) m[f2] = mp[f2];
        float s0[4], s1[4];
#pragma unroll
        for (int c = 0; c < 4; c++) {
            s0[c] = m[c] + m[4 + c] + m[8 + c];
            s1[c] = m[4 + c] - m[8 + c] - m[12 + c];
        }
        float y00 = s0[0] + s0[1] + s0[2], y01 = s0[1] - s0[2] - s0[3];
        float y10 = s1[0] + s1[1] + s1[2], y11 = s1[1] - s1[2] - s1[3];
        int co = cog * 16 + col;
        float sc = scale[co], sh = shift[co];
        float* op = out + obase + (size_t)co * 1568 + (2 * ti) * 14 + 2 * tj;
        op[0]  = gelu_exact(y00 * sc + sh);
        op[1]  = gelu_exact(y01 * sc + sh);
        op[14] = gelu_exact(y10 * sc + sh);
        op[15] = gelu_exact(y11 * sc + sh);
    }
}

// ---------------- kernel 8: transpose y2 -> row-major [(pix,bt)][c] --------
__global__ void transpose_y2_kernel() {
    int e = blockIdx.x * 256 + threadIdx.x;
    float v = g_y2[e];
    int pix = e % 196;
    int t = (e / 196) & 7;
    int c = (e / 1568) & 63;
    int b = e / (1568 * 64);
    g_y2t[((size_t)(pix * 128 + b * 8 + t)) * 64 + c] = v;
}

// ---------------- kernel 9: output GEMM (25088 x 64 -> 768) + bias ---------
__global__ void gemm_out_kernel(const float* __restrict__ Wo,
                                const float* __restrict__ bvec,
                                float* __restrict__ out) {
    __shared__ float YsT[64 * 72];
    __shared__ float WoT[64 * 72];
    int tid = threadIdx.x;
    int row0 = blockIdx.x * 64, col0 = blockIdx.y * 64;
#pragma unroll
    for (int i = 0; i < 16; i++) {
        int e = tid + i * 256;
        int r = e >> 6, k = e & 63;
        YsT[k * 72 + r] = g_y2t[(size_t)(row0 + r) * 64 + k];
        WoT[k * 72 + r] = Wo[(size_t)(col0 + r) * 64 + k];
    }
    __syncthreads();
    int ty = tid >> 4, tx = tid & 15;
    ull acc2[2][4] = {};
#pragma unroll 4
    for (int k = 0; k < 64; k++) {
        ulonglong2 a2 = *(const ulonglong2*)(YsT + k * 72 + ty * 4);
        float4 bq = *(const float4*)(WoT + k * 72 + tx * 4);
        ull b0 = pack2(bq.x, bq.x), b1 = pack2(bq.y, bq.y);
        ull b2 = pack2(bq.z, bq.z), b3 = pack2(bq.w, bq.w);
        ffma2(acc2[0][0], a2.x, b0); ffma2(acc2[0][1], a2.x, b1);
        ffma2(acc2[0][2], a2.x, b2); ffma2(acc2[0][3], a2.x, b3);
        ffma2(acc2[1][0], a2.y, b0); ffma2(acc2[1][1], a2.y, b1);
        ffma2(acc2[1][2], a2.y, b2); ffma2(acc2[1][3], a2.y, b3);
    }
    float accf[4][4];
#pragma unroll
    for (int i2 = 0; i2 < 2; i2++)
#pragma unroll
        for (int j = 0; j < 4; j++) {
            float2 v = unpack2(acc2[i2][j]);
            accf[2 * i2][j] = v.x;
            accf[2 * i2 + 1][j] = v.y;
        }
    float b0 = bvec[col0 + tx * 4 + 0];
    float b1 = bvec[col0 + tx * 4 + 1];
    float b2 = bvec[col0 + tx * 4 + 2];
    float b3 = bvec[col0 + tx * 4 + 3];
#pragma unroll
    for (int i = 0; i < 4; i++) {
        int r = row0 + ty * 4 + i;
        float4 v;
        v.x = accf[i][0] + b0;
        v.y = accf[i][1] + b1;
        v.z = accf[i][2] + b2;
        v.w = accf[i][3] + b3;
        *(float4*)(out + (size_t)r * 768 + col0 + tx * 4) = v;
    }
}

// ---------------- launch ---------------------------------------------------
extern "C" void kernel_launch(void* const* d_in, const int* in_sizes, int n_in,
                              void* d_out, int out_size) {
    const float* x         = (const float*)d_in[0];
    const float* ln_gamma  = (const float*)d_in[1];
    const float* ln_beta   = (const float*)d_in[2];
    const float* in_w      = (const float*)d_in[3];
    const float* in_b      = (const float*)d_in[4];
    const float* ext_w     = (const float*)d_in[5];
    const float* ext_scale = (const float*)d_in[6];
    const float* ext_shift = (const float*)d_in[7];
    const float* i0_w      = (const float*)d_in[8];
    const float* i0_scale  = (const float*)d_in[9];
    const float* i0_shift  = (const float*)d_in[10];
    const float* i1_w      = (const float*)d_in[11];
    const float* i1_scale  = (const float*)d_in[12];
    const float* i1_shift  = (const float*)d_in[13];
    const float* i2_w      = (const float*)d_in[14];
    const float* i2_scale  = (const float*)d_in[15];
    const float* i2_shift  = (const float*)d_in[16];
    const float* out_w     = (const float*)d_in[17];
    const float* out_b     = (const float*)d_in[18];
    float* out = (float*)d_out;

    cudaFuncSetAttribute(corr_kernel,         cudaFuncAttributeMaxDynamicSharedMemorySize, 50176);
    cudaFuncSetAttribute(ext_kernel,          cudaFuncAttributeMaxDynamicSharedMemorySize, 52488);
    cudaFuncSetAttribute(wino_conv_kernel<0>, cudaFuncAttributeMaxDynamicSharedMemorySize, 90112);
    cudaFuncSetAttribute(wino_conv_kernel<1>, cudaFuncAttributeMaxDynamicSharedMemorySize, 90112);
    cudaFuncSetAttribute(wino_conv_kernel<2>, cudaFuncAttributeMaxDynamicSharedMemorySize, 90112);

    prep_w_kernel<<<64, 256>>>(in_w, ln_gamma, ln_beta, in_b);
    wino_w_kernel<<<80, 256>>>(i0_w, i1_w, i2_w);
    gemm_in_kernel<<<392, 256>>>(x);
    corr_kernel<<<640, 224, 50176>>>();
    ext_kernel<<<dim3(640, 2), 224, 52488>>>(ext_w, ext_scale, ext_shift);
    wino_conv_kernel<0><<<dim3(640, 4), 896, 90112>>>(i0_scale, i0_shift);
    wino_conv_kernel<1><<<dim3(640, 4), 896, 90112>>>(i1_scale, i1_shift);
    wino_conv_kernel<2><<<dim3(128, 4), 896, 90112>>>(i2_scale, i2_shift);
    transpose_y2_kernel<<<6272, 256>>>();
    gemm_out_kernel<<<dim3(392, 12), 256>>>(out_w, out_b, out);
}

// round 12
// speedup vs baseline: 1.7722x; 1.7722x over previous
#include <cuda_runtime.h>
#include <math.h>

// Problem constants
#define LNUM 196      // H*W
#define BTN  128      // B*T
#define DIM  768
#define NDH  64
#define NT   8
#define NB   16
#define NH   14
#define NLW  5
#define NROWS 25088   // LNUM*BTN
#define NF   640      // B*T*Lw frames

typedef unsigned long long ull;

// ---------------- scratch (device globals: allocation-free) ----------------
__device__ float g_Wg[NDH * DIM];
__device__ float g_A[NDH];
__device__ float g_Bc[NDH];
__device__ float g_fn[BTN * LNUM * NDH];          // normalized features [bt][pix][c]
__device__ float g_yext[80 * 64 * 8 * 196];        // [(b*5+l)*64+c][t][pix]
__device__ float g_y0[80 * 64 * 8 * 196];
__device__ float g_y1[80 * 64 * 8 * 196];
__device__ float g_y2t[(size_t)NROWS * 64];        // [(pix*128+bt)][c]
// ci-PAIRED conv weights: [ci2][tap][co][2]  (pair = adjacent input channels)
__device__ float g_w0p[32 * 9 * 64 * 2];
__device__ float g_w1p[32 * 9 * 64 * 2];
__device__ float g_w2p[160 * 9 * 64 * 2];

__device__ __forceinline__ float gelu_exact(float x) {
    return 0.5f * x * (1.0f + erff(x * 0.70710678118654752f));
}

// ---- packed f32x2 helpers (FFMA2: saves issue slots) ----
__device__ __forceinline__ void ffma2(ull& d, ull a, ull b) {
    asm("fma.rn.f32x2 %0, %1, %2, %0;" : "+l"(d) : "l"(a), "l"(b));
}
__device__ __forceinline__ ull pack2(float lo, float hi) {
    ull r; asm("mov.b64 %0, {%1, %2};" : "=l"(r) : "f"(lo), "f"(hi)); return r;
}
__device__ __forceinline__ float2 unpack2(ull v) {
    float lo, hi; asm("mov.b64 {%0, %1}, %2;" : "=f"(lo), "=f"(hi) : "l"(v));
    return make_float2(lo, hi);
}

// ---------------- kernel 0: fold layernorm gamma/beta into projection ------
__global__ void prep_w_kernel(const float* __restrict__ in_w,
                              const float* __restrict__ gamma,
                              const float* __restrict__ beta,
                              const float* __restrict__ in_b) {
    int c = blockIdx.x;
    int tid = threadIdx.x;
    float pa = 0.f, pb = 0.f;
    for (int d = tid; d < DIM; d += 256) {
        float w  = in_w[c * DIM + d];
        float wg = w * gamma[d];
        g_Wg[c * DIM + d] = wg;
        pa += wg;
        pb += w * beta[d];
    }
    __shared__ float rA[256], rB[256];
    rA[tid] = pa; rB[tid] = pb;
    __syncthreads();
    for (int s = 128; s > 0; s >>= 1) {
        if (tid < s) { rA[tid] += rA[tid + s]; rB[tid] += rB[tid + s]; }
        __syncthreads();
    }
    if (tid == 0) { g_A[c] = rA[0]; g_Bc[c] = rB[0] + in_b[c]; }
}

// ---------------- kernel 0b: build ci-paired conv weights ------------------
__global__ void transpose_w_kernel(const float* __restrict__ i0w,
                                   const float* __restrict__ i1w,
                                   const float* __restrict__ i2w) {
    int e = blockIdx.x * 256 + threadIdx.x;
    if (e < 36864) {
        int par = e & 1, rest = e >> 1;
        int co = rest & 63;
        int tap = (rest >> 6) % 9;
        int ci = (rest / 576) * 2 + par;
        g_w0p[e] = i0w[(co * 64 + ci) * 9 + tap];
        g_w1p[e] = i1w[(co * 64 + ci) * 9 + tap];
    }
    if (e < 184320) {
        int par = e & 1, rest = e >> 1;
        int co = rest & 63;
        int tap = (rest >> 6) % 9;
        int ci = (rest / 576) * 2 + par;
        g_w2p[e] = i2w[(co * 320 + ci) * 9 + tap];
    }
}

// ---------------- kernel 2: input GEMM + fused LN stats + normalize --------
__global__ void gemm_in_kernel(const float* __restrict__ x) {
    __shared__ float XsT[32 * 72];
    __shared__ float WsT[32 * 72];
    __shared__ float Sv[64][65];
    __shared__ float Srow[64][4];
    __shared__ float Sinv[64];
    __shared__ float s_mu[64];
    __shared__ float s_rs[64];
    int tid = threadIdx.x;
    int ty = tid >> 4, tx = tid & 15;
    int w = tid >> 5, lane = tid & 31;
    int row0 = blockIdx.x * 64;
    ull acc2[2][4] = {};
    float sumv[8] = {}, sqv[8] = {};
    float xr[8], wr[8];
#pragma unroll
    for (int i = 0; i < 8; i++) {
        int e = tid + i * 256;
        int r = e >> 5, k = e & 31;
        xr[i] = x[(size_t)(row0 + r) * DIM + k];
        wr[i] = g_Wg[r * DIM + k];
    }
    for (int kb = 0; kb < DIM; kb += 32) {
#pragma unroll
        for (int i = 0; i < 8; i++) {
            int e = tid + i * 256;
            int r = e >> 5, k = e & 31;
            XsT[k * 72 + r] = xr[i];
            WsT[k * 72 + r] = wr[i];
            sumv[i] += xr[i];
            sqv[i]  += xr[i] * xr[i];
        }
        __syncthreads();
        if (kb + 32 < DIM) {
#pragma unroll
            for (int i = 0; i < 8; i++) {
                int e = tid + i * 256;
                int r = e >> 5, k = e & 31;
                xr[i] = x[(size_t)(row0 + r) * DIM + kb + 32 + k];
                wr[i] = g_Wg[r * DIM + kb + 32 + k];
            }
        }
#pragma unroll 4
        for (int k = 0; k < 32; k++) {
            ulonglong2 a2 = *(const ulonglong2*)(XsT + k * 72 + ty * 4);
            float4 bq = *(const float4*)(WsT + k * 72 + tx * 4);
            ull b0 = pack2(bq.x, bq.x), b1 = pack2(bq.y, bq.y);
            ull b2 = pack2(bq.z, bq.z), b3 = pack2(bq.w, bq.w);
            ffma2(acc2[0][0], a2.x, b0); ffma2(acc2[0][1], a2.x, b1);
            ffma2(acc2[0][2], a2.x, b2); ffma2(acc2[0][3], a2.x, b3);
            ffma2(acc2[1][0], a2.y, b0); ffma2(acc2[1][1], a2.y, b1);
            ffma2(acc2[1][2], a2.y, b2); ffma2(acc2[1][3], a2.y, b3);
        }
        __syncthreads();
    }
#pragma unroll
    for (int i = 0; i < 8; i++) {
        for (int o = 16; o > 0; o >>= 1) {
            sumv[i] += __shfl_xor_sync(0xffffffffu, sumv[i], o);
            sqv[i]  += __shfl_xor_sync(0xffffffffu, sqv[i],  o);
        }
    }
    if (lane == 0) {
#pragma unroll
        for (int i = 0; i < 8; i++) {
            int r = w + 8 * i;
            float mu  = sumv[i] * (1.0f / DIM);
            float var = sqv[i] * (1.0f / DIM) - mu * mu;
            s_mu[r] = mu;
            s_rs[r] = rsqrtf(var + 1e-5f);
        }
    }
    __syncthreads();
    float accf[4][4];
#pragma unroll
    for (int i2 = 0; i2 < 2; i2++)
#pragma unroll
        for (int j = 0; j < 4; j++) {
            float2 v = unpack2(acc2[i2][j]);
            accf[2 * i2][j] = v.x;
            accf[2 * i2 + 1][j] = v.y;
        }
#pragma unroll
    for (int i = 0; i < 4; i++) {
        int rl = ty * 4 + i;
        float rs = s_rs[rl], mu = s_mu[rl];
#pragma unroll
        for (int j = 0; j < 4; j++) {
            int c = tx * 4 + j;
            Sv[rl][c] = rs * accf[i][j] - rs * mu * g_A[c] + g_Bc[c];
        }
    }
    __syncthreads();
    {
        int row = tid >> 2, q = tid & 3;
        float s = 0.f;
#pragma unroll
        for (int c = 0; c < 16; c++) { float v = Sv[row][q * 16 + c]; s += v * v; }
        Srow[row][q] = s;
    }
    __syncthreads();
    if (tid < 64) {
        float n = Srow[tid][0] + Srow[tid][1] + Srow[tid][2] + Srow[tid][3];
        Sinv[tid] = 1.0f / fmaxf(sqrtf(n), 1e-7f);
    }
    __syncthreads();
#pragma unroll
    for (int i = 0; i < 16; i++) {
        int e = tid + i * 256;
        int row = e >> 6, c = e & 63;
        int r = row0 + row;
        int l = r >> 7, bt = r & 127;
        g_fn[((size_t)bt * LNUM + l) * NDH + c] = Sv[row][c] * Sinv[row];
    }
}

// ---------------- kernel 3: fused local correlation + ext 1x1 + BN-GELU ----
// grid 640 frames, block 224. smem: s_tgt[12544] | s_corr[15876] | s_w[5184]
__global__ void corr_ext_kernel(const float* __restrict__ ew,
                                const float* __restrict__ scale,
                                const float* __restrict__ shift) {
    extern __shared__ float sm[];
    float* s_tgt  = sm;            // [c2=32][2*196]
    float* s_corr = sm + 12544;    // [pix=196][81]
    float* s_w    = sm + 28420;    // [k=81][co=64]
    int fidx = blockIdx.x;
    int b = fidx / 40, rem = fidx % 40;
    int t = rem / 5, l = rem % 5;
    int ttg = t + l - 2;
    int tid = threadIdx.x;
    size_t obase = ((size_t)(b * 5 + l) * 64) * 1568 + (size_t)t * 196;
    if (ttg < 0 || ttg >= NT) {    // temporal zero-pad: corr==0 -> gelu(shift)
        for (int e = tid; e < 12544; e += 224) {
            int co = e & 63, p = e >> 6;
            g_yext[obase + (size_t)co * 1568 + p] = gelu_exact(shift[co]);
        }
        return;
    }
    // stage weights [k][co]
    for (int e = tid; e < 5184; e += 224) {
        int k = e >> 6, co = e & 63;
        s_w[e] = ew[co * 81 + k];
    }
    // stage + transpose target frame (channel-pair interleaved)
    const float* tgt = g_fn + (size_t)(b * 8 + ttg) * (196 * 64);
    for (int e = tid; e < 3136; e += 224) {
        int p = e >> 4, c4 = e & 15;
        float4 v = *(const float4*)(tgt + p * 64 + c4 * 4);
        *(float2*)(s_tgt + (c4 * 2 + 0) * 392 + 2 * p) = make_float2(v.x, v.y);
        *(float2*)(s_tgt + (c4 * 2 + 1) * 392 + 2 * p) = make_float2(v.z, v.w);
    }
    __syncthreads();
    // correlation into smem
    if (tid < 196) {
        int h = tid / 14, w = tid % 14;
        const float4* src = (const float4*)(g_fn + ((size_t)(b * 8 + t) * 196 + tid) * 64);
        ull s2[32];
#pragma unroll
        for (int i = 0; i < 16; i++) {
            float4 v = src[i];
            s2[i * 2 + 0] = pack2(v.x, v.y);
            s2[i * 2 + 1] = pack2(v.z, v.w);
        }
        float* op = s_corr + tid * 81;
#pragma unroll 1
        for (int du = 0; du < 9; du++) {
            int uh = h + du - 4;
            bool rok = (uh >= 0) && (uh < 14);
#pragma unroll 1
            for (int dv = 0; dv < 9; dv++) {
                int vw = w + dv - 4;
                float acc = 0.0f;
                if (rok && vw >= 0 && vw < 14) {
                    const float* tp = s_tgt + 2 * (uh * 14 + vw);
                    ull a2 = 0ull;
#pragma unroll
                    for (int c2 = 0; c2 < 32; c2++) {
                        ull tv = *(const ull*)(tp + c2 * 392);
                        ffma2(a2, s2[c2], tv);
                    }
                    float2 r = unpack2(a2);
                    acc = r.x + r.y;
                }
                op[du * 9 + dv] = acc;
            }
        }
    }
    __syncthreads();
    // ext projection: 28 pixel-groups(7 px) x 8 co-groups(8 co)
    {
        int plg = tid >> 3, coq = tid & 7;
        float acc[7][8] = {};
        const float* scp = s_corr + plg * 7 * 81;
        const float* swp = s_w + coq * 8;
#pragma unroll 3
        for (int k = 0; k < 81; k++) {
            float4 wa = *(const float4*)(swp + k * 64);
            float4 wb = *(const float4*)(swp + k * 64 + 4);
#pragma unroll
            for (int i = 0; i < 7; i++) {
                float cv = scp[i * 81 + k];
                acc[i][0] += cv * wa.x; acc[i][1] += cv * wa.y;
                acc[i][2] += cv * wa.z; acc[i][3] += cv * wa.w;
                acc[i][4] += cv * wb.x; acc[i][5] += cv * wb.y;
                acc[i][6] += cv * wb.z; acc[i][7] += cv * wb.w;
            }
        }
        size_t ob = obase + plg * 7;
#pragma unroll
        for (int j = 0; j < 8; j++) {
            int co = coq * 8 + j;
            float scv = scale[co], shv = shift[co];
#pragma unroll
            for (int i = 0; i < 7; i++)
                g_yext[ob + (size_t)co * 1568 + i] = gelu_exact(acc[i][j] * scv + shv);
        }
    }
}

// ---------------- kernels 5/6: 3x3 conv 64->64, ci-pair FFMA2 (mov-free) ---
// grid 640 (f x t), block 448 = 14 rows x 2 halves x 16 co-groups(4 co)
template <int WHICH>
__global__ void __launch_bounds__(448, 1)
conv64_kernel(const float* __restrict__ scale,
              const float* __restrict__ shift) {
    extern __shared__ float sm[];
    float* s_in = sm;
    float* s_w  = sm + 8192;
    const float* in = (WHICH == 0) ? g_yext : g_y0;
    const float* Wp = (WHICH == 0) ? g_w0p  : g_w1p;
    float* out      = (WHICH == 0) ? g_y0   : g_y1;
    int f = blockIdx.x >> 3, t = blockIdx.x & 7;
    int tid = threadIdx.x;
    int cog = tid & 15;
    int half = (tid >> 4) & 1;
    int row = tid >> 5;
    int px0 = half * 7;
    const float* inb = in + (size_t)(f * 512 + t) * 196;
    ull acc2[7][4] = {};
    for (int cb = 0; cb < 2; cb++) {
        __syncthreads();
        for (int e = tid; e < 8192; e += 448) s_in[e] = 0.0f;
        __syncthreads();
        for (int e = tid; e < 6272; e += 448) {
            int c = e / 196, p = e % 196;
            s_in[(c >> 1) * 512 + ((p / 14) + 1) * 32 + ((p % 14) + 1) * 2 + (c & 1)] =
                inb[(size_t)(cb * 32 + c) * 1568 + p];
        }
        {
            const float4* srcw = (const float4*)(Wp + cb * 18432);
            float4* dstw = (float4*)s_w;
            for (int e = tid; e < 4608; e += 448) dstw[e] = srcw[e];
        }
        __syncthreads();
#pragma unroll 1
        for (int ci2 = 0; ci2 < 16; ci2++) {
            const float* wp = s_w + ci2 * 1152 + cog * 8;
#pragma unroll
            for (int dh = 0; dh < 3; dh++) {
                const ull* bp = (const ull*)(s_in + (ci2 * 16 + row + dh) * 32 + px0 * 2);
                ull win2[9];
#pragma unroll
                for (int j = 0; j < 9; j++) win2[j] = bp[j];
#pragma unroll
                for (int dw = 0; dw < 3; dw++) {
                    const float* wpt = wp + (dh * 3 + dw) * 128;
                    ulonglong2 wa = *(const ulonglong2*)(wpt);
                    ulonglong2 wb = *(const ulonglong2*)(wpt + 4);
#pragma unroll
                    for (int p = 0; p < 7; p++) {
                        ull iv = win2[p + dw];
                        ffma2(acc2[p][0], iv, wa.x);
                        ffma2(acc2[p][1], iv, wa.y);
                        ffma2(acc2[p][2], iv, wb.x);
                        ffma2(acc2[p][3], iv, wb.y);
                    }
                }
            }
        }
    }
    float* ob = out + (size_t)(f * 512 + t) * 196 + row * 14 + px0;
#pragma unroll
    for (int j = 0; j < 4; j++) {
        int co = cog * 4 + j;
        float scv = scale[co], shv = shift[co];
#pragma unroll
        for (int p = 0; p < 7; p++) {
            float2 v = unpack2(acc2[p][j]);
            ob[(size_t)co * 1568 + p] = gelu_exact((v.x + v.y) * scv + shv);
        }
    }
}

// ---------------- kernel 7: i2 3x3 conv 320->64 + fused transpose ----------
// grid (128 slices, 2 co-halves), block 448; writes g_y2t[(pix*128+bt)][c]
__global__ void __launch_bounds__(448, 2)
conv320_kernel(const float* __restrict__ scale,
               const float* __restrict__ shift) {
    extern __shared__ float sm[];
    float* s_in = sm;
    float* s_w  = sm + 8192;
    int slice = blockIdx.x;
    int b = slice >> 3, t = slice & 7;
    int coh = blockIdx.y;
    int tid = threadIdx.x;
    int cog = tid & 15;
    int half = (tid >> 4) & 1;
    int row = tid >> 5;
    int px0 = half * 7;
    ull acc2[7][2] = {};
    for (int cb = 0; cb < 10; cb++) {
        __syncthreads();
        for (int e = tid; e < 8192; e += 448) s_in[e] = 0.0f;
        __syncthreads();
        for (int e = tid; e < 6272; e += 448) {
            int c = e / 196, p = e % 196;
            s_in[(c >> 1) * 512 + ((p / 14) + 1) * 32 + ((p % 14) + 1) * 2 + (c & 1)] =
                g_y1[(size_t)((b * 320 + cb * 32 + c) * 8 + t) * 196 + p];
        }
        {
            const ull* srcw = (const ull*)g_w2p;
            ull* dstw = (ull*)s_w;
            for (int e = tid; e < 4608; e += 448) {
                int ci2l = e / 288, r = e % 288, tap = r >> 5, col = r & 31;
                dstw[(ci2l * 9 + tap) * 32 + col] =
                    srcw[((cb * 16 + ci2l) * 9 + tap) * 64 + coh * 32 + col];
            }
        }
        __syncthreads();
#pragma unroll 1
        for (int ci2 = 0; ci2 < 16; ci2++) {
            const float* wp = s_w + ci2 * 576 + cog * 4;
#pragma unroll
            for (int dh = 0; dh < 3; dh++) {
                const ull* bp = (const ull*)(s_in + (ci2 * 16 + row + dh) * 32 + px0 * 2);
                ull win2[9];
#pragma unroll
                for (int j = 0; j < 9; j++) win2[j] = bp[j];
#pragma unroll
                for (int dw = 0; dw < 3; dw++) {
                    ulonglong2 wq = *(const ulonglong2*)(wp + (dh * 3 + dw) * 64);
#pragma unroll
                    for (int p = 0; p < 7; p++) {
                        ull iv = win2[p + dw];
                        ffma2(acc2[p][0], iv, wq.x);
                        ffma2(acc2[p][1], iv, wq.y);
                    }
                }
            }
        }
    }
    int pixb = row * 14 + px0;
    int bt = b * 8 + t;
#pragma unroll
    for (int j = 0; j < 2; j++) {
        int co = coh * 32 + cog * 2 + j;
        float scv = scale[co], shv = shift[co];
#pragma unroll
        for (int p = 0; p < 7; p++) {
            float2 v = unpack2(acc2[p][j]);
            g_y2t[((size_t)(pixb + p) * 128 + bt) * 64 + co] =
                gelu_exact((v.x + v.y) * scv + shv);
        }
    }
}

// ---------------- kernel 9: output GEMM (25088 x 64 -> 768) + bias ---------
__global__ void gemm_out_kernel(const float* __restrict__ Wo,
                                const float* __restrict__ bvec,
                                float* __restrict__ out) {
    __shared__ float YsT[64 * 72];
    __shared__ float WoT[64 * 72];
    int tid = threadIdx.x;
    int row0 = blockIdx.x * 64, col0 = blockIdx.y * 64;
#pragma unroll
    for (int i = 0; i < 16; i++) {
        int e = tid + i * 256;
        int r = e >> 6, k = e & 63;
        YsT[k * 72 + r] = g_y2t[(size_t)(row0 + r) * 64 + k];
        WoT[k * 72 + r] = Wo[(size_t)(col0 + r) * 64 + k];
    }
    __syncthreads();
    int ty = tid >> 4, tx = tid & 15;
    ull acc2[2][4] = {};
#pragma unroll 4
    for (int k = 0; k < 64; k++) {
        ulonglong2 a2 = *(const ulonglong2*)(YsT + k * 72 + ty * 4);
        float4 bq = *(const float4*)(WoT + k * 72 + tx * 4);
        ull b0 = pack2(bq.x, bq.x), b1 = pack2(bq.y, bq.y);
        ull b2 = pack2(bq.z, bq.z), b3 = pack2(bq.w, bq.w);
        ffma2(acc2[0][0], a2.x, b0); ffma2(acc2[0][1], a2.x, b1);
        ffma2(acc2[0][2], a2.x, b2); ffma2(acc2[0][3], a2.x, b3);
        ffma2(acc2[1][0], a2.y, b0); ffma2(acc2[1][1], a2.y, b1);
        ffma2(acc2[1][2], a2.y, b2); ffma2(acc2[1][3], a2.y, b3);
    }
    float accf[4][4];
#pragma unroll
    for (int i2 = 0; i2 < 2; i2++)
#pragma unroll
        for (int j = 0; j < 4; j++) {
            float2 v = unpack2(acc2[i2][j]);
            accf[2 * i2][j] = v.x;
            accf[2 * i2 + 1][j] = v.y;
        }
    float b0 = bvec[col0 + tx * 4 + 0];
    float b1 = bvec[col0 + tx * 4 + 1];
    float b2 = bvec[col0 + tx * 4 + 2];
    float b3 = bvec[col0 + tx * 4 + 3];
#pragma unroll
    for (int i = 0; i < 4; i++) {
        int r = row0 + ty * 4 + i;
        float4 v;
        v.x = accf[i][0] + b0;
        v.y = accf[i][1] + b1;
        v.z = accf[i][2] + b2;
        v.w = accf[i][3] + b3;
        *(float4*)(out + (size_t)r * 768 + col0 + tx * 4) = v;
    }
}

// ---------------- launch ---------------------------------------------------
extern "C" void kernel_launch(void* const* d_in, const int* in_sizes, int n_in,
                              void* d_out, int out_size) {
    const float* x         = (const float*)d_in[0];
    const float* ln_gamma  = (const float*)d_in[1];
    const float* ln_beta   = (const float*)d_in[2];
    const float* in_w      = (const float*)d_in[3];
    const float* in_b      = (const float*)d_in[4];
    const float* ext_w     = (const float*)d_in[5];
    const float* ext_scale = (const float*)d_in[6];
    const float* ext_shift = (const float*)d_in[7];
    const float* i0_w      = (const float*)d_in[8];
    const float* i0_scale  = (const float*)d_in[9];
    const float* i0_shift  = (const float*)d_in[10];
    const float* i1_w      = (const float*)d_in[11];
    const float* i1_scale  = (const float*)d_in[12];
    const float* i1_shift  = (const float*)d_in[13];
    const float* i2_w      = (const float*)d_in[14];
    const float* i2_scale  = (const float*)d_in[15];
    const float* i2_shift  = (const float*)d_in[16];
    const float* out_w     = (const float*)d_in[17];
    const float* out_b     = (const float*)d_in[18];
    float* out = (float*)d_out;

    cudaFuncSetAttribute(corr_ext_kernel,  cudaFuncAttributeMaxDynamicSharedMemorySize, 134416);
    cudaFuncSetAttribute(conv64_kernel<0>, cudaFuncAttributeMaxDynamicSharedMemorySize, 106496);
    cudaFuncSetAttribute(conv64_kernel<1>, cudaFuncAttributeMaxDynamicSharedMemorySize, 106496);
    cudaFuncSetAttribute(conv320_kernel,   cudaFuncAttributeMaxDynamicSharedMemorySize, 69632);

    prep_w_kernel<<<64, 256>>>(in_w, ln_gamma, ln_beta, in_b);
    transpose_w_kernel<<<720, 256>>>(i0_w, i1_w, i2_w);
    gemm_in_kernel<<<392, 256>>>(x);
    corr_ext_kernel<<<640, 224, 134416>>>(ext_w, ext_scale, ext_shift);
    conv64_kernel<0><<<640, 448, 106496>>>(i0_scale, i0_shift);
    conv64_kernel<1><<<640, 448, 106496>>>(i1_scale, i1_shift);
    conv320_kernel<<<dim3(128, 2), 448, 69632>>>(i2_scale, i2_shift);
    gemm_out_kernel<<<dim3(392, 12), 256>>>(out_w, out_b, out);
}